// round 16
// baseline (speedup 1.0000x reference)
#include <cuda_runtime.h>
#include <cstdint>
#include <cstddef>

// Problem constants (fixed shapes)
#define BATCH   4
#define SEQ     1024
#define NHEADS  32
#define NKV     8
#define HDIM    128
#define NTOK    (BATCH * SEQ)
#define NBLOCKS 32

#define BM 128         // q rows per CTA (8 warps x 16 rows)
#define BN 64          // keys per iteration
#define NTHREADS 256
#define NSTAGE 3
#define NQT (SEQ / BM) // 8

// scale = float(bfloat16(1/sqrt(128))) = 0.08837890625; folded with log2(e), into Q
#define SCALE_LOG2E 0.1274994096f

#define O_ELEMS     ((size_t)NTOK * NHEADS * HDIM)           // 16,777,216
#define CACHE_ELEMS ((size_t)NBLOCKS * 256 * NKV * HDIM)     // 8,388,608

// Pre-converted K/V in MMA B-fragment order, tf32 bits (R9 layout).
#define NCHUNK   512
#define CH_U32   8192
__device__ uint32_t g_Kf[(size_t)NCHUNK * CH_U32];   // 16 MB
__device__ uint32_t g_Vf[(size_t)NCHUNK * CH_U32];   // 16 MB

#define TILE_U32  CH_U32                             // 8192 u32 = 32 KB per tile
#define SMEM_BYTES (NSTAGE * 2 * TILE_U32 * 4)       // 196,608 B

__device__ __forceinline__ uint32_t f2tf32(float f) {
    uint32_t u;
    asm("cvt.rna.tf32.f32 %0, %1;" : "=r"(u) : "f"(f));
    return u;
}
__device__ __forceinline__ float fexp2(float x) {
    float y;
    asm("ex2.approx.f32 %0, %1;" : "=f"(y) : "f"(x));
    return y;
}
__device__ __forceinline__ void mma_tf32(float c[4],
                                         uint32_t a0, uint32_t a1, uint32_t a2, uint32_t a3,
                                         uint32_t b0, uint32_t b1) {
    asm volatile(
        "mma.sync.aligned.m16n8k8.row.col.f32.tf32.tf32.f32 "
        "{%0,%1,%2,%3}, {%4,%5,%6,%7}, {%8,%9}, {%0,%1,%2,%3};"
        : "+f"(c[0]), "+f"(c[1]), "+f"(c[2]), "+f"(c[3])
        : "r"(a0), "r"(a1), "r"(a2), "r"(a3), "r"(b0), "r"(b1));
}
__device__ __forceinline__ void cp16(uint32_t dst, const void* src) {
    asm volatile("cp.async.cg.shared.global [%0], [%1], 16;" :: "r"(dst), "l"(src));
}

// ---------------------------------------------------------------------------
// Prepass: convert K,V -> tf32 bits in B-fragment order (identical to R9).
// ---------------------------------------------------------------------------
__global__ __launch_bounds__(256)
void prep_kernel(const float* __restrict__ k, const float* __restrict__ v)
{
    const int c   = blockIdx.x;       // 0..511
    const int kt  = c & 15;
    const int kvh = (c >> 4) & 7;
    const int b   = c >> 7;
    const float* kb = k + ((size_t)(b * SEQ + kt * 64) * NKV + kvh) * HDIM;
    const float* vb = v + ((size_t)(b * SEQ + kt * 64) * NKV + kvh) * HDIM;
    uint32_t* ok = g_Kf + (size_t)c * CH_U32;
    uint32_t* ov = g_Vf + (size_t)c * CH_U32;

    #pragma unroll 4
    for (int i = threadIdx.x; i < CH_U32; i += 256) {
        const int r  = i & 1;
        const int ln = (i >> 1) & 31;
        {   // K frag: i = ((kc*8 + nt)*32 + lane)*2 + r
            const int nt = (i >> 6) & 7;
            const int kc = i >> 9;
            const int key = nt * 8 + (ln >> 2);
            const int d   = kc * 8 + (ln & 3) + 4 * r;
            ok[i] = f2tf32(kb[(size_t)key * NKV * HDIM + d]);
        }
        {   // V frag: i = ((kc2*16 + nt2)*32 + lane)*2 + r
            const int nt2 = (i >> 6) & 15;
            const int kc2 = i >> 10;
            const int key = kc2 * 8 + (ln & 3) + 4 * r;
            const int d   = nt2 * 8 + (ln >> 2);
            ov[i] = f2tf32(vb[(size_t)key * NKV * HDIM + d]);
        }
    }
}

// ---------------------------------------------------------------------------
// Fused kernel. grid = (NQT + 1, NHEADS, BATCH), block = 256.
//  x == 0 : cache copy + slot scatter (128 CTAs)
//  x >= 1 : flash attention, TF32 mma.sync, no-rescale softmax,
//           3-stage cp.async ring, HALF-TILE PIPELINED compute:
//           per 32-key half: GEMM1 -> softmax -> GEMM2 (finer phase grain
//           so the 2 warps/SMSP anti-phase instead of stalling in lockstep).
// ---------------------------------------------------------------------------
__global__ __launch_bounds__(NTHREADS, 1)
void fused_attn_kernel(const float* __restrict__ q,
                       const float* __restrict__ k,
                       const float* __restrict__ v,
                       const float* __restrict__ kc,
                       const float* __restrict__ vc,
                       const int*   __restrict__ slot_mapping,
                       float* __restrict__ o,
                       float* __restrict__ okc,
                       float* __restrict__ ovc)
{
    __shared__ int sh_toks[NTHREADS];
    __shared__ int sh_slts[NTHREADS];
    __shared__ int sh_n;

    const int tid = threadIdx.x;

    // ================= copy + scatter lane =================
    if (blockIdx.x == 0) {
        const int c = blockIdx.y * BATCH + blockIdx.z;   // 0..127
        {
            const float4* s_k = (const float4*)kc + (size_t)c * 16384;
            const float4* s_v = (const float4*)vc + (size_t)c * 16384;
            float4* d_k = (float4*)okc + (size_t)c * 16384;
            float4* d_v = (float4*)ovc + (size_t)c * 16384;
            #pragma unroll 4
            for (int i = tid; i < 16384; i += NTHREADS) {
                d_k[i] = s_k[i];
                d_v[i] = s_v[i];
            }
        }
        __syncthreads();
        const int s0 = c * 64, s1 = s0 + 64;
        for (int base = 0; base < NTOK; base += NTHREADS) {
            const int t = base + tid;
            const int s = slot_mapping[t];
            const bool hit = (s >= s0) && (s < s1);
            if (tid == 0) sh_n = 0;
            __syncthreads();
            if (hit) {
                const int idx = atomicAdd(&sh_n, 1);
                sh_toks[idx] = t;
                sh_slts[idx] = s;
            }
            __syncthreads();
            const int nh = sh_n;
            for (int u = 0; u < nh; ++u) {
                const int tt = sh_toks[u];
                const int ss = sh_slts[u];
                const float4* sk = (const float4*)(k + (size_t)tt * NKV * HDIM);
                const float4* sv = (const float4*)(v + (size_t)tt * NKV * HDIM);
                float4* dk = (float4*)(okc + (size_t)ss * NKV * HDIM);
                float4* dv = (float4*)(ovc + (size_t)ss * NKV * HDIM);
                if (tid < 256) {
                    dk[tid] = sk[tid];
                    dv[tid] = sv[tid];
                }
            }
            __syncthreads();
        }
        return;
    }

    // ================= attention lane =================
    extern __shared__ uint32_t smem[];
    uint32_t* KS = smem;                        // [NSTAGE][TILE_U32]
    uint32_t* VS = smem + NSTAGE * TILE_U32;    // [NSTAGE][TILE_U32]
    const uint32_t ks_base = (uint32_t)__cvta_generic_to_shared(KS);
    const uint32_t vs_base = (uint32_t)__cvta_generic_to_shared(VS);

    const int qt  = NQT - (int)blockIdx.x;      // x=1 -> qt=7 (heavy first)
    const int h   = blockIdx.y;
    const int b   = blockIdx.z;
    const int kvh = h >> 2;                     // GQA: N_REP=4

    const int warp = tid >> 5;
    const int lane = tid & 31;
    const int g    = lane >> 2;
    const int tg   = lane & 3;

    const uint32_t* kfb = g_Kf + (size_t)((b * NKV + kvh) * 16) * CH_U32;
    const uint32_t* vfb = g_Vf + (size_t)((b * NKV + kvh) * 16) * CH_U32;

    // ---- Q fragments into registers (A frags m16n8k8, tf32, scale folded) ----
    uint32_t qa[16][4];
    {
        const float* qbase = q + ((size_t)(b * SEQ + qt * BM + warp * 16) * NHEADS + h) * HDIM;
        #pragma unroll
        for (int kc2 = 0; kc2 < 16; ++kc2) {
            #pragma unroll
            for (int e = 0; e < 4; ++e) {
                const int R = g + 8 * (e & 1);
                const int C = kc2 * 8 + tg + 4 * (e >> 1);
                qa[kc2][e] = f2tf32(qbase[(size_t)R * NHEADS * HDIM + C] * SCALE_LOG2E);
            }
        }
    }

    float oacc[16][4];
    #pragma unroll
    for (int t = 0; t < 16; ++t) {
        oacc[t][0] = 0.f; oacc[t][1] = 0.f; oacc[t][2] = 0.f; oacc[t][3] = 0.f;
    }
    float l0 = 0.f, l1 = 0.f;

    const int nkt   = 2 * (qt + 1);
    const int wbase = qt * BM + warp * 16;
    const int row0  = wbase + g;
    const int row1  = row0 + 8;
    const int src0  = (lane & ~3) | (tg >> 1);
    const int src1  = src0 + 2;

    // ---- prologue: stage tiles 0 and 1 ----
    #pragma unroll
    for (int pt = 0; pt < 2; ++pt) {
        const uint32_t* ksrc = kfb + (size_t)pt * CH_U32;
        const uint32_t* vsrc = vfb + (size_t)pt * CH_U32;
        const uint32_t kd = ks_base + (uint32_t)(pt * TILE_U32) * 4;
        const uint32_t vd = vs_base + (uint32_t)(pt * TILE_U32) * 4;
        #pragma unroll
        for (int it = 0; it < 8; ++it) {
            const int u = (tid + it * NTHREADS) * 4;
            cp16(kd + (uint32_t)u * 4, ksrc + u);
            cp16(vd + (uint32_t)u * 4, vsrc + u);
        }
        asm volatile("cp.async.commit_group;");
    }

    for (int kt = 0; kt < nkt; ++kt) {
        const int n0 = kt * BN;
        const int buf  = kt % 3;
        const int pbuf = (kt + 2) % 3;

        asm volatile("cp.async.wait_group 1;");
        __syncthreads();   // tile kt visible CTA-wide; buf (kt+2)%3 reusable

        // ---- prefetch tile kt+2 into pbuf ----
        if (kt + 2 < nkt) {
            const uint32_t* ksrc = kfb + (size_t)(kt + 2) * CH_U32;
            const uint32_t* vsrc = vfb + (size_t)(kt + 2) * CH_U32;
            const uint32_t kd = ks_base + (uint32_t)(pbuf * TILE_U32) * 4;
            const uint32_t vd = vs_base + (uint32_t)(pbuf * TILE_U32) * 4;
            #pragma unroll
            for (int it = 0; it < 8; ++it) {
                const int u = (tid + it * NTHREADS) * 4;
                cp16(kd + (uint32_t)u * 4, ksrc + u);
                cp16(vd + (uint32_t)u * 4, vsrc + u);
            }
        }
        asm volatile("cp.async.commit_group;");

        const uint32_t* Kt = KS + buf * TILE_U32;
        const uint32_t* Vt = VS + buf * TILE_U32;

        // ---- half-tile pipelined compute: 32 keys per half ----
        #pragma unroll
        for (int hf = 0; hf < 2; ++hf) {
            const int h0 = n0 + hf * 32;           // first key of this half
            if (h0 > wbase + 15) break;            // fully masked: skip

            // GEMM1 half: S[16 x 32] over n-tiles hf*4 .. hf*4+3
            float s[4][4];
            #pragma unroll
            for (int nt = 0; nt < 4; ++nt) {
                s[nt][0] = 0.f; s[nt][1] = 0.f; s[nt][2] = 0.f; s[nt][3] = 0.f;
            }
            #pragma unroll
            for (int kc2 = 0; kc2 < 16; ++kc2) {
                #pragma unroll
                for (int nt = 0; nt < 4; ++nt) {
                    const uint2 bb =
                        *(const uint2*)&Kt[(((kc2 * 8 + hf * 4 + nt) * 32) + lane) * 2];
                    mma_tf32(s[nt], qa[kc2][0], qa[kc2][1], qa[kc2][2], qa[kc2][3],
                             bb.x, bb.y);
                }
            }

            // softmax half: p = 2^s, masked -> 0; in place as tf32 bits
            const bool need_mask = (h0 + 31 > wbase);
            #pragma unroll
            for (int nt = 0; nt < 4; ++nt) {
                float p0 = fexp2(s[nt][0]);
                float p1 = fexp2(s[nt][1]);
                float p2 = fexp2(s[nt][2]);
                float p3 = fexp2(s[nt][3]);
                if (need_mask) {
                    const int c0 = h0 + nt * 8 + 2 * tg;
                    if (c0 > row0)     p0 = 0.f;
                    if (c0 + 1 > row0) p1 = 0.f;
                    if (c0 > row1)     p2 = 0.f;
                    if (c0 + 1 > row1) p3 = 0.f;
                }
                l0 += p0 + p1;
                l1 += p2 + p3;
                s[nt][0] = __uint_as_float(f2tf32(p0));
                s[nt][1] = __uint_as_float(f2tf32(p1));
                s[nt][2] = __uint_as_float(f2tf32(p2));
                s[nt][3] = __uint_as_float(f2tf32(p3));
            }

            // GEMM2 half: O += P[:, this half] . V[this half, :]
            #pragma unroll
            for (int j = 0; j < 4; ++j) {
                const int kc2 = hf * 4 + j;        // global key-group
                const uint32_t t00 = __shfl_sync(0xffffffffu, __float_as_uint(s[j][0]), src0);
                const uint32_t t01 = __shfl_sync(0xffffffffu, __float_as_uint(s[j][1]), src0);
                const uint32_t t10 = __shfl_sync(0xffffffffu, __float_as_uint(s[j][2]), src0);
                const uint32_t t11 = __shfl_sync(0xffffffffu, __float_as_uint(s[j][3]), src0);
                const uint32_t u00 = __shfl_sync(0xffffffffu, __float_as_uint(s[j][0]), src1);
                const uint32_t u01 = __shfl_sync(0xffffffffu, __float_as_uint(s[j][1]), src1);
                const uint32_t u10 = __shfl_sync(0xffffffffu, __float_as_uint(s[j][2]), src1);
                const uint32_t u11 = __shfl_sync(0xffffffffu, __float_as_uint(s[j][3]), src1);
                const uint32_t a0 = (tg & 1) ? t01 : t00;
                const uint32_t a1 = (tg & 1) ? t11 : t10;
                const uint32_t a2 = (tg & 1) ? u01 : u00;
                const uint32_t a3 = (tg & 1) ? u11 : u10;
                #pragma unroll
                for (int nt2 = 0; nt2 < 16; ++nt2) {
                    const uint2 bb =
                        *(const uint2*)&Vt[(((kc2 * 16 + nt2) * 32) + lane) * 2];
                    mma_tf32(oacc[nt2], a0, a1, a2, a3, bb.x, bb.y);
                }
            }
        }
    }

    // ---- final row-sum reduction ----
    l0 += __shfl_xor_sync(0xffffffffu, l0, 1);
    l0 += __shfl_xor_sync(0xffffffffu, l0, 2);
    l1 += __shfl_xor_sync(0xffffffffu, l1, 1);
    l1 += __shfl_xor_sync(0xffffffffu, l1, 2);
    const float inv0 = 1.0f / l0;
    const float inv1 = 1.0f / l1;

    // ---- epilogue: normalize, store ----
    float* ob = o + ((size_t)(b * SEQ + row0) * NHEADS + h) * HDIM;
    #pragma unroll
    for (int nt2 = 0; nt2 < 16; ++nt2) {
        const int d = nt2 * 8 + 2 * tg;
        float2 v0; v0.x = oacc[nt2][0] * inv0; v0.y = oacc[nt2][1] * inv0;
        float2 v1; v1.x = oacc[nt2][2] * inv1; v1.y = oacc[nt2][3] * inv1;
        *(float2*)&ob[d] = v0;
        *(float2*)&ob[(size_t)8 * NHEADS * HDIM + d] = v1;
    }
}

// ---------------------------------------------------------------------------
// kernel_launch: inputs in metadata order
//   0 q, 1 k, 2 v, 3 k_cache, 4 v_cache, 5 slot_mapping, 6/7 cu_seqlens (unused)
// output: concat(o [4096,4096], k_cache, v_cache) f32
// ---------------------------------------------------------------------------
extern "C" void kernel_launch(void* const* d_in, const int* in_sizes, int n_in,
                              void* d_out, int out_size)
{
    const float* q    = (const float*)d_in[0];
    const float* k    = (const float*)d_in[1];
    const float* v    = (const float*)d_in[2];
    const float* kc   = (const float*)d_in[3];
    const float* vc   = (const float*)d_in[4];
    const int*   slot = (const int*)d_in[5];

    float* out = (float*)d_out;
    float* o   = out;
    float* okc = out + O_ELEMS;
    float* ovc = okc + CACHE_ELEMS;

    prep_kernel<<<NCHUNK, 256>>>(k, v);

    cudaFuncSetAttribute(fused_attn_kernel,
                         cudaFuncAttributeMaxDynamicSharedMemorySize, SMEM_BYTES);

    dim3 grid(NQT + 1, NHEADS, BATCH);
    fused_attn_kernel<<<grid, NTHREADS, SMEM_BYTES>>>(q, k, v, kc, vc, slot,
                                                      o, okc, ovc);
}

// round 17
// speedup vs baseline: 1.5712x; 1.5712x over previous
#include <cuda_runtime.h>
#include <cuda_fp16.h>
#include <cstdint>
#include <cstddef>

// Problem constants (fixed shapes)
#define BATCH   4
#define SEQ     1024
#define NHEADS  32
#define NKV     8
#define HDIM    128
#define NTOK    (BATCH * SEQ)
#define NBLOCKS 32

#define BM 128         // q rows per CTA (8 warps x 16 rows)
#define BN 64          // keys per iteration
#define NTHREADS 256
#define NSTAGE 3
#define NQT (SEQ / BM) // 8

// scale = float(bfloat16(1/sqrt(128))) = 0.08837890625; folded with log2(e), into Q
#define SCALE_LOG2E 0.1274994096f

#define O_ELEMS     ((size_t)NTOK * NHEADS * HDIM)           // 16,777,216
#define CACHE_ELEMS ((size_t)NBLOCKS * 256 * NKV * HDIM)     // 8,388,608

// Pre-converted K/V in fp16 MMA B-fragment order (m16n8k16), packed half2.
// K chunk u32 i = ((kc*8 + nt)*32 + ln)*2 + r   (kc 0..7, nt 0..7)
//   -> half2{ K[key][d0], K[key][d0+1] }, key = nt*8+(ln>>2), d0 = kc*16+8r+2(ln&3)
// V chunk u32 i = ((kc2*16 + nt2)*32 + ln)*2 + r (kc2 0..3, nt2 0..15)
//   -> half2{ V[k0][d], V[k0+1][d] }, k0 = kc2*16+8r+2(ln&3), d = nt2*8+(ln>>2)
#define NCHUNK   512
#define CH_U32   4096                                 // 16 KB per tile per tensor
__device__ uint32_t g_Kf[(size_t)NCHUNK * CH_U32];    // 8 MB
__device__ uint32_t g_Vf[(size_t)NCHUNK * CH_U32];    // 8 MB

#define TILE_U32  CH_U32
#define SMEM_BYTES (NSTAGE * 2 * TILE_U32 * 4)        // 98,304 B

__device__ __forceinline__ uint32_t f2h2(float lo, float hi) {
    __half2 h = __floats2half2_rn(lo, hi);   // .x = lo (low half), .y = hi
    return *(uint32_t*)&h;
}
__device__ __forceinline__ float fexp2(float x) {
    float y;
    asm("ex2.approx.f32 %0, %1;" : "=f"(y) : "f"(x));
    return y;
}
__device__ __forceinline__ void mma_f16(float c[4],
                                        uint32_t a0, uint32_t a1, uint32_t a2, uint32_t a3,
                                        uint32_t b0, uint32_t b1) {
    asm volatile(
        "mma.sync.aligned.m16n8k16.row.col.f32.f16.f16.f32 "
        "{%0,%1,%2,%3}, {%4,%5,%6,%7}, {%8,%9}, {%0,%1,%2,%3};"
        : "+f"(c[0]), "+f"(c[1]), "+f"(c[2]), "+f"(c[3])
        : "r"(a0), "r"(a1), "r"(a2), "r"(a3), "r"(b0), "r"(b1));
}
__device__ __forceinline__ void cp16(uint32_t dst, const void* src) {
    asm volatile("cp.async.cg.shared.global [%0], [%1], 16;" :: "r"(dst), "l"(src));
}

// ---------------------------------------------------------------------------
// Prepass: K,V -> fp16 (rn) in m16n8k16 B-fragment order.
// grid = 512: c -> (b, kvh, kt of 64 keys). 256 threads.
// ---------------------------------------------------------------------------
__global__ __launch_bounds__(256)
void prep_kernel(const float* __restrict__ k, const float* __restrict__ v)
{
    __shared__ float sm[64 * 132];
    const int c   = blockIdx.x;       // 0..511
    const int kt  = c & 15;
    const int kvh = (c >> 4) & 7;
    const int b   = c >> 7;
    const float* kb = k + ((size_t)(b * SEQ + kt * 64) * NKV + kvh) * HDIM;
    const float* vb = v + ((size_t)(b * SEQ + kt * 64) * NKV + kvh) * HDIM;
    uint32_t* ok = g_Kf + (size_t)c * CH_U32;
    uint32_t* ov = g_Vf + (size_t)c * CH_U32;

    // stage V rows into smem (coalesced) for the key-pair packing below
    #pragma unroll 4
    for (int i = threadIdx.x; i < 64 * HDIM; i += 256) {
        const int n = i >> 7, d = i & 127;
        sm[n * 132 + d] = vb[(size_t)n * NKV * HDIM + d];
    }
    __syncthreads();

    #pragma unroll 4
    for (int i = threadIdx.x; i < CH_U32; i += 256) {
        const int r  = i & 1;
        const int ln = (i >> 1) & 31;
        {   // K: half2 of consecutive d
            const int nt = (i >> 6) & 7;
            const int kc = i >> 9;                  // 0..7
            const int key = nt * 8 + (ln >> 2);
            const int d0  = kc * 16 + 8 * r + 2 * (ln & 3);
            const float* kp = kb + (size_t)key * NKV * HDIM + d0;
            ok[i] = f2h2(kp[0], kp[1]);
        }
        {   // V: half2 of consecutive keys (same d), from smem
            const int nt2 = (i >> 6) & 15;
            const int kc2 = i >> 10;                // 0..3
            const int k0  = kc2 * 16 + 8 * r + 2 * (ln & 3);
            const int d   = nt2 * 8 + (ln >> 2);
            ov[i] = f2h2(sm[k0 * 132 + d], sm[(k0 + 1) * 132 + d]);
        }
    }
}

// ---------------------------------------------------------------------------
// Fused kernel. grid = (NQT + 1, NHEADS, BATCH), block = 256.
//  x == 0 : cache copy + slot scatter (128 CTAs)
//  x >= 1 : flash attention, fp16 m16n8k16 MMA (fp32 accum), no-rescale
//           softmax, 3-stage cp.async ring, zero shuffles (C->A is a
//           register repack).
// ---------------------------------------------------------------------------
__global__ __launch_bounds__(NTHREADS, 1)
void fused_attn_kernel(const float* __restrict__ q,
                       const float* __restrict__ k,
                       const float* __restrict__ v,
                       const float* __restrict__ kc,
                       const float* __restrict__ vc,
                       const int*   __restrict__ slot_mapping,
                       float* __restrict__ o,
                       float* __restrict__ okc,
                       float* __restrict__ ovc)
{
    __shared__ int sh_toks[NTHREADS];
    __shared__ int sh_slts[NTHREADS];
    __shared__ int sh_n;

    const int tid = threadIdx.x;

    // ================= copy + scatter lane =================
    if (blockIdx.x == 0) {
        const int c = blockIdx.y * BATCH + blockIdx.z;   // 0..127
        {
            const float4* s_k = (const float4*)kc + (size_t)c * 16384;
            const float4* s_v = (const float4*)vc + (size_t)c * 16384;
            float4* d_k = (float4*)okc + (size_t)c * 16384;
            float4* d_v = (float4*)ovc + (size_t)c * 16384;
            #pragma unroll 4
            for (int i = tid; i < 16384; i += NTHREADS) {
                d_k[i] = s_k[i];
                d_v[i] = s_v[i];
            }
        }
        __syncthreads();
        const int s0 = c * 64, s1 = s0 + 64;
        for (int base = 0; base < NTOK; base += NTHREADS) {
            const int t = base + tid;
            const int s = slot_mapping[t];
            const bool hit = (s >= s0) && (s < s1);
            if (tid == 0) sh_n = 0;
            __syncthreads();
            if (hit) {
                const int idx = atomicAdd(&sh_n, 1);
                sh_toks[idx] = t;
                sh_slts[idx] = s;
            }
            __syncthreads();
            const int nh = sh_n;
            for (int u = 0; u < nh; ++u) {
                const int tt = sh_toks[u];
                const int ss = sh_slts[u];
                const float4* sk = (const float4*)(k + (size_t)tt * NKV * HDIM);
                const float4* sv = (const float4*)(v + (size_t)tt * NKV * HDIM);
                float4* dk = (float4*)(okc + (size_t)ss * NKV * HDIM);
                float4* dv = (float4*)(ovc + (size_t)ss * NKV * HDIM);
                if (tid < 256) {
                    dk[tid] = sk[tid];
                    dv[tid] = sv[tid];
                }
            }
            __syncthreads();
        }
        return;
    }

    // ================= attention lane =================
    extern __shared__ uint32_t smem[];
    uint32_t* KS = smem;                        // [NSTAGE][TILE_U32]
    uint32_t* VS = smem + NSTAGE * TILE_U32;    // [NSTAGE][TILE_U32]
    const uint32_t ks_base = (uint32_t)__cvta_generic_to_shared(KS);
    const uint32_t vs_base = (uint32_t)__cvta_generic_to_shared(VS);

    const int qt  = NQT - (int)blockIdx.x;      // x=1 -> qt=7 (heavy first)
    const int h   = blockIdx.y;
    const int b   = blockIdx.z;
    const int kvh = h >> 2;                     // GQA: N_REP=4

    const int warp = tid >> 5;
    const int lane = tid & 31;
    const int g    = lane >> 2;
    const int tg   = lane & 3;

    const uint32_t* kfb = g_Kf + (size_t)((b * NKV + kvh) * 16) * CH_U32;
    const uint32_t* vfb = g_Vf + (size_t)((b * NKV + kvh) * 16) * CH_U32;

    // ---- Q A-fragments (m16n8k16) in registers, fp16, scale folded ----
    // qa[kc][0]={Q[g][C],Q[g][C+1]}, [1]=rows g+8, [2]=cols C+8, [3]=both
    uint32_t qa[8][4];
    {
        const float* qbase = q + ((size_t)(b * SEQ + qt * BM + warp * 16) * NHEADS + h) * HDIM;
        const float* qr0 = qbase + (size_t)g * NHEADS * HDIM;
        const float* qr1 = qbase + (size_t)(g + 8) * NHEADS * HDIM;
        #pragma unroll
        for (int kc2 = 0; kc2 < 8; ++kc2) {
            const int C0 = kc2 * 16 + 2 * tg;
            qa[kc2][0] = f2h2(qr0[C0] * SCALE_LOG2E,     qr0[C0 + 1] * SCALE_LOG2E);
            qa[kc2][1] = f2h2(qr1[C0] * SCALE_LOG2E,     qr1[C0 + 1] * SCALE_LOG2E);
            qa[kc2][2] = f2h2(qr0[C0 + 8] * SCALE_LOG2E, qr0[C0 + 9] * SCALE_LOG2E);
            qa[kc2][3] = f2h2(qr1[C0 + 8] * SCALE_LOG2E, qr1[C0 + 9] * SCALE_LOG2E);
        }
    }

    float oacc[16][4];
    #pragma unroll
    for (int t = 0; t < 16; ++t) {
        oacc[t][0] = 0.f; oacc[t][1] = 0.f; oacc[t][2] = 0.f; oacc[t][3] = 0.f;
    }
    float l0 = 0.f, l1 = 0.f;

    const int nkt   = 2 * (qt + 1);
    const int wbase = qt * BM + warp * 16;
    const int row0  = wbase + g;
    const int row1  = row0 + 8;

    // ---- prologue: stage tiles 0 and 1 (4 x 16B per tensor per thread) ----
    #pragma unroll
    for (int pt = 0; pt < 2; ++pt) {
        const uint32_t* ksrc = kfb + (size_t)pt * CH_U32;
        const uint32_t* vsrc = vfb + (size_t)pt * CH_U32;
        const uint32_t kd = ks_base + (uint32_t)(pt * TILE_U32) * 4;
        const uint32_t vd = vs_base + (uint32_t)(pt * TILE_U32) * 4;
        #pragma unroll
        for (int it = 0; it < 4; ++it) {
            const int u = (tid + it * NTHREADS) * 4;
            cp16(kd + (uint32_t)u * 4, ksrc + u);
            cp16(vd + (uint32_t)u * 4, vsrc + u);
        }
        asm volatile("cp.async.commit_group;");
    }

    for (int kt = 0; kt < nkt; ++kt) {
        const int n0 = kt * BN;
        const int buf  = kt % 3;
        const int pbuf = (kt + 2) % 3;

        asm volatile("cp.async.wait_group 1;");
        __syncthreads();   // tile kt visible CTA-wide; buf (kt+2)%3 reusable

        // ---- prefetch tile kt+2 into pbuf ----
        if (kt + 2 < nkt) {
            const uint32_t* ksrc = kfb + (size_t)(kt + 2) * CH_U32;
            const uint32_t* vsrc = vfb + (size_t)(kt + 2) * CH_U32;
            const uint32_t kd = ks_base + (uint32_t)(pbuf * TILE_U32) * 4;
            const uint32_t vd = vs_base + (uint32_t)(pbuf * TILE_U32) * 4;
            #pragma unroll
            for (int it = 0; it < 4; ++it) {
                const int u = (tid + it * NTHREADS) * 4;
                cp16(kd + (uint32_t)u * 4, ksrc + u);
                cp16(vd + (uint32_t)u * 4, vsrc + u);
            }
        }
        asm volatile("cp.async.commit_group;");

        // warps whose rows are all < n0 have a fully-masked tile: skip compute
        if (n0 <= wbase + 15) {
            const uint32_t* Kt = KS + buf * TILE_U32;
            const uint32_t* Vt = VS + buf * TILE_U32;

            // ---- GEMM1: S[16 x 64] = Q . K^T (8 k-steps of 16) ----
            float s[8][4];
            #pragma unroll
            for (int nt = 0; nt < 8; ++nt) {
                s[nt][0] = 0.f; s[nt][1] = 0.f; s[nt][2] = 0.f; s[nt][3] = 0.f;
            }
            #pragma unroll
            for (int kc2 = 0; kc2 < 8; ++kc2) {
                #pragma unroll
                for (int nt = 0; nt < 8; ++nt) {
                    const uint2 bb = *(const uint2*)&Kt[(((kc2 * 8 + nt) * 32) + lane) * 2];
                    mma_f16(s[nt], qa[kc2][0], qa[kc2][1], qa[kc2][2], qa[kc2][3],
                            bb.x, bb.y);
                }
            }

            // ---- no-rescale softmax + pack P into m16n8k16 A-frags ----
            // C layout: c0=(g,2tg) c1=(g,2tg+1) c2=(g+8,2tg) c3=(g+8,2tg+1)
            // A-frag for GEMM2 k-step kc2: S-tiles 2kc2 (cols 0-7) and 2kc2+1 (cols 8-15)
            const bool need_mask = (n0 + BN - 1 > wbase);
            uint32_t pa[4][4];
            #pragma unroll
            for (int kc2 = 0; kc2 < 4; ++kc2) {
                #pragma unroll
                for (int j = 0; j < 2; ++j) {
                    const int nt = 2 * kc2 + j;
                    float p0 = fexp2(s[nt][0]);
                    float p1 = fexp2(s[nt][1]);
                    float p2 = fexp2(s[nt][2]);
                    float p3 = fexp2(s[nt][3]);
                    if (need_mask) {
                        const int c0 = n0 + nt * 8 + 2 * tg;
                        if (c0 > row0)     p0 = 0.f;
                        if (c0 + 1 > row0) p1 = 0.f;
                        if (c0 > row1)     p2 = 0.f;
                        if (c0 + 1 > row1) p3 = 0.f;
                    }
                    l0 += p0 + p1;
                    l1 += p2 + p3;
                    pa[kc2][2 * j]     = f2h2(p0, p1);   // row g
                    pa[kc2][2 * j + 1] = f2h2(p2, p3);   // row g+8
                }
            }

            // ---- GEMM2: O[16 x 128] += P . V (4 k-steps of 16 keys) ----
            #pragma unroll
            for (int kc2 = 0; kc2 < 4; ++kc2) {
                #pragma unroll
                for (int nt2 = 0; nt2 < 16; ++nt2) {
                    const uint2 bb = *(const uint2*)&Vt[(((kc2 * 16 + nt2) * 32) + lane) * 2];
                    mma_f16(oacc[nt2], pa[kc2][0], pa[kc2][1], pa[kc2][2], pa[kc2][3],
                            bb.x, bb.y);
                }
            }
        }
    }

    // ---- final row-sum reduction (over the 4 lanes of each quad) ----
    l0 += __shfl_xor_sync(0xffffffffu, l0, 1);
    l0 += __shfl_xor_sync(0xffffffffu, l0, 2);
    l1 += __shfl_xor_sync(0xffffffffu, l1, 1);
    l1 += __shfl_xor_sync(0xffffffffu, l1, 2);
    const float inv0 = 1.0f / l0;
    const float inv1 = 1.0f / l1;

    // ---- epilogue: normalize, store ----
    float* ob = o + ((size_t)(b * SEQ + row0) * NHEADS + h) * HDIM;
    #pragma unroll
    for (int nt2 = 0; nt2 < 16; ++nt2) {
        const int d = nt2 * 8 + 2 * tg;
        float2 v0; v0.x = oacc[nt2][0] * inv0; v0.y = oacc[nt2][1] * inv0;
        float2 v1; v1.x = oacc[nt2][2] * inv1; v1.y = oacc[nt2][3] * inv1;
        *(float2*)&ob[d] = v0;
        *(float2*)&ob[(size_t)8 * NHEADS * HDIM + d] = v1;
    }
}

// ---------------------------------------------------------------------------
// kernel_launch: inputs in metadata order
//   0 q, 1 k, 2 v, 3 k_cache, 4 v_cache, 5 slot_mapping, 6/7 cu_seqlens (unused)
// output: concat(o [4096,4096], k_cache, v_cache) f32
// ---------------------------------------------------------------------------
extern "C" void kernel_launch(void* const* d_in, const int* in_sizes, int n_in,
                              void* d_out, int out_size)
{
    const float* q    = (const float*)d_in[0];
    const float* k    = (const float*)d_in[1];
    const float* v    = (const float*)d_in[2];
    const float* kc   = (const float*)d_in[3];
    const float* vc   = (const float*)d_in[4];
    const int*   slot = (const int*)d_in[5];

    float* out = (float*)d_out;
    float* o   = out;
    float* okc = out + O_ELEMS;
    float* ovc = okc + CACHE_ELEMS;

    prep_kernel<<<NCHUNK, 256>>>(k, v);

    cudaFuncSetAttribute(fused_attn_kernel,
                         cudaFuncAttributeMaxDynamicSharedMemorySize, SMEM_BYTES);

    dim3 grid(NQT + 1, NHEADS, BATCH);
    fused_attn_kernel<<<grid, NTHREADS, SMEM_BYTES>>>(q, k, v, kc, vc, slot,
                                                      o, okc, ovc);
}